// round 3
// baseline (speedup 1.0000x reference)
#include <cuda_runtime.h>
#include <cstdint>

// BinCat: idx = sum_j (1 - x[b,i,j]) * 2^(19-j), out[row,:] = cats[idx,:]
// x:    (4096, 16, 20) int32 (0/1)  -> 65536 rows of 80 B (int4-aligned)
// cats: (2^20, 64) float32          -> 256 B rows (2 full 128B lines)
// out:  (4096, 16, 64) float32
//
// R3 design: one warp handles 32 rows.
//   Phase 1: lane l computes the index of row base+l via 5 independent
//            int4 loads (MLP=5, hides DRAM + TLB latency).
//   Phase 2: fully-unrolled 32-iteration cooperative gather; each
//            iteration is an independent 256B row copy (float2/lane).
//            Unrolling lets ptxas batch many LDGs -> deep MLP, which is
//            what the R2 profile showed we lack (DRAM 20%, issue 18%).

static constexpr int LENGTH = 20;
static constexpr int DIM    = 64;

__global__ void __launch_bounds__(256)
bincat_gather_kernel(const int* __restrict__ x,
                     const float* __restrict__ cats,
                     float* __restrict__ out,
                     int nrows)
{
    const int gtid     = blockIdx.x * blockDim.x + threadIdx.x;
    const int warp_id  = gtid >> 5;
    const int lane     = threadIdx.x & 31;
    const int row_base = warp_id * 32;      // this warp owns rows [row_base, row_base+32)
    if (row_base >= nrows) return;

    // ---- Phase 1: per-lane index computation (rows are 80 B = 5 x int4) ----
    const int myrow = row_base + lane;
    unsigned idx = 0u;
    if (myrow < nrows) {
        const int4* __restrict__ xr =
            reinterpret_cast<const int4*>(x + (size_t)myrow * LENGTH);
        int4 a0 = __ldg(&xr[0]);
        int4 a1 = __ldg(&xr[1]);
        int4 a2 = __ldg(&xr[2]);
        int4 a3 = __ldg(&xr[3]);
        int4 a4 = __ldg(&xr[4]);
        const int v[LENGTH] = { a0.x, a0.y, a0.z, a0.w,
                                a1.x, a1.y, a1.z, a1.w,
                                a2.x, a2.y, a2.z, a2.w,
                                a3.x, a3.y, a3.z, a3.w,
                                a4.x, a4.y, a4.z, a4.w };
        #pragma unroll
        for (int j = 0; j < LENGTH; ++j) {
            // x is 0/1; (1 - x_j) selects bit with weight 2^(19-j).
            idx |= (unsigned)(1 - v[j]) << (LENGTH - 1 - j);
        }
    }

    // ---- Phase 2: cooperative gather of 32 rows (256 B each) ----
    // Fully unrolled so ptxas batches independent LDGs (deep MLP).
    #pragma unroll
    for (int i = 0; i < 32; ++i) {
        const int r = row_base + i;
        if (r >= nrows) break;
        const unsigned ridx = __shfl_sync(0xffffffffu, idx, i);
        const float2* __restrict__ src =
            reinterpret_cast<const float2*>(cats + (size_t)ridx * DIM);
        float2* __restrict__ dst =
            reinterpret_cast<float2*>(out + (size_t)r * DIM);
        dst[lane] = __ldg(&src[lane]);
    }
}

extern "C" void kernel_launch(void* const* d_in, const int* in_sizes, int n_in,
                              void* d_out, int out_size)
{
    const int*   x    = (const int*)d_in[0];    // (B, I, 20) int32
    const float* cats = (const float*)d_in[1];  // (2^20, 64) float32
    float*       out  = (float*)d_out;          // (B, I, 64) float32

    const int nrows = in_sizes[0] / LENGTH;     // 65536

    const int threads = 256;                    // 8 warps/block
    const int rows_per_block = (threads / 32) * 32;   // 256 rows
    const int blocks = (nrows + rows_per_block - 1) / rows_per_block;

    bincat_gather_kernel<<<blocks, threads>>>(x, cats, out, nrows);
}

// round 4
// speedup vs baseline: 1.4963x; 1.4963x over previous
#include <cuda_runtime.h>
#include <cstdint>

// BinCat: idx = sum_j (1 - x[b,i,j]) * 2^(19-j), out[row,:] = cats[idx,:]
// x:    (4096, 16, 20) int32 (0/1)  -> 65536 rows of 80 B (int4-aligned)
// cats: (2^20, 64) float32           -> 256 B rows (2 full 128B lines)
// out:  (4096, 16, 64) float32
//
// R4 design: one warp handles 8 rows (R3's 32-rows/warp collapsed the grid
// to 256 CTAs -> occ 19%; R2's 1-row/warp had MLP=1 -> latency-bound).
//   Phase 1: lanes 0..7 each compute one row index (5 independent int4
//            loads each, combined with disjoint-bit ORs).
//   Phase 2: LOAD-ALL (8 independent 256B row reads -> 16 cache lines in
//            flight per warp) then STORE-ALL. Explicit staging registers
//            force ptxas to front-batch the LDGs.
// Grid = 1024 CTAs x 8 warps = 8192 warps; ~16 lines/warp in flight.

static constexpr int LENGTH = 20;
static constexpr int DIM    = 64;
static constexpr int ROWS_PER_WARP = 8;

__global__ void __launch_bounds__(256)
bincat_gather_kernel(const int* __restrict__ x,
                     const float* __restrict__ cats,
                     float* __restrict__ out,
                     int nrows)
{
    const int gtid     = blockIdx.x * blockDim.x + threadIdx.x;
    const int warp_id  = gtid >> 5;
    const int lane     = threadIdx.x & 31;
    const int row_base = warp_id * ROWS_PER_WARP;
    if (row_base >= nrows) return;

    // ---- Phase 1: lanes 0..7 compute indices (rows are 80 B = 5 x int4) ----
    unsigned idx = 0u;
    if (lane < ROWS_PER_WARP) {
        const int myrow = row_base + lane;
        if (myrow < nrows) {
            const int4* __restrict__ xr =
                reinterpret_cast<const int4*>(x + (size_t)myrow * LENGTH);
            // 5 independent loads issue back-to-back (MLP=5)
            const int4 a0 = __ldg(&xr[0]);
            const int4 a1 = __ldg(&xr[1]);
            const int4 a2 = __ldg(&xr[2]);
            const int4 a3 = __ldg(&xr[3]);
            const int4 a4 = __ldg(&xr[4]);
            const int v[LENGTH] = { a0.x, a0.y, a0.z, a0.w,
                                    a1.x, a1.y, a1.z, a1.w,
                                    a2.x, a2.y, a2.z, a2.w,
                                    a3.x, a3.y, a3.z, a3.w,
                                    a4.x, a4.y, a4.z, a4.w };
            #pragma unroll
            for (int j = 0; j < LENGTH; ++j)
                idx |= (unsigned)(1 - v[j]) << (LENGTH - 1 - j);
        }
    }

    // ---- Phase 2a: broadcast indices, issue ALL gather loads ----
    unsigned ridx[ROWS_PER_WARP];
    #pragma unroll
    for (int i = 0; i < ROWS_PER_WARP; ++i)
        ridx[i] = __shfl_sync(0xffffffffu, idx, i);

    float2 v[ROWS_PER_WARP];
    #pragma unroll
    for (int i = 0; i < ROWS_PER_WARP; ++i) {
        const float2* __restrict__ src =
            reinterpret_cast<const float2*>(cats + (size_t)ridx[i] * DIM);
        v[i] = __ldg(&src[lane]);           // 8 independent 256B reads
    }

    // ---- Phase 2b: store all rows (coalesced, fire-and-forget) ----
    #pragma unroll
    for (int i = 0; i < ROWS_PER_WARP; ++i) {
        const int r = row_base + i;
        if (r < nrows) {
            float2* __restrict__ dst =
                reinterpret_cast<float2*>(out + (size_t)r * DIM);
            dst[lane] = v[i];
        }
    }
}

extern "C" void kernel_launch(void* const* d_in, const int* in_sizes, int n_in,
                              void* d_out, int out_size)
{
    const int*   x    = (const int*)d_in[0];    // (B, I, 20) int32
    const float* cats = (const float*)d_in[1];  // (2^20, 64) float32
    float*       out  = (float*)d_out;          // (B, I, 64) float32

    const int nrows = in_sizes[0] / LENGTH;     // 65536

    const int threads = 256;                                    // 8 warps
    const int rows_per_block = (threads / 32) * ROWS_PER_WARP;  // 64 rows
    const int blocks = (nrows + rows_per_block - 1) / rows_per_block;  // 1024

    bincat_gather_kernel<<<blocks, threads>>>(x, cats, out, nrows);
}